// round 1
// baseline (speedup 1.0000x reference)
#include <cuda_runtime.h>
#include <math.h>

#define TINF 3.0e38f
#define TT   1024
#define BB   32
#define DDIM 64
#define NDIAG (2*TT-1)   // 2047

// Scratch: diag-major cost [b][d][j], d padded to 2048. 256 MB.
__device__ float g_cost[(size_t)BB * 2048 * TT];
__device__ float g_n2[2 * BB * TT];   // a2 (first half) then b2
__device__ float g_bdist[BB];

// ---------------------------------------------------------------------------
// Kernel 1: squared row norms. One warp per 64-dim row.
// ---------------------------------------------------------------------------
__global__ void norms_kernel(const float* __restrict__ pred,
                             const float* __restrict__ targ) {
    int gw   = (blockIdx.x * blockDim.x + threadIdx.x) >> 5;  // global warp id
    int lane = threadIdx.x & 31;
    if (gw >= 2 * BB * TT) return;
    const float* src = (gw < BB * TT) ? (pred + (size_t)gw * DDIM)
                                      : (targ + (size_t)(gw - BB * TT) * DDIM);
    float x0 = src[lane], x1 = src[lane + 32];
    float s = x0 * x0 + x1 * x1;
    #pragma unroll
    for (int o = 16; o > 0; o >>= 1) s += __shfl_down_sync(0xffffffffu, s, o);
    if (lane == 0) g_n2[gw] = s;
}

// ---------------------------------------------------------------------------
// Kernel 2: cost tiles. 64x64 tile per block (256 threads, 4x4 microtile),
// epilogue stages the tile in smem and writes diagonal-major runs (coalesced).
// ---------------------------------------------------------------------------
__global__ void __launch_bounds__(256) cost_kernel(const float* __restrict__ pred,
                                                   const float* __restrict__ targ) {
    int jt = blockIdx.x, it = blockIdx.y, b = blockIdx.z;
    int i0 = it * 64, j0 = jt * 64;
    const float* A  = pred + (size_t)b * TT * DDIM;
    const float* Bm = targ + (size_t)b * TT * DDIM;

    __shared__ float sm[8192];          // sA[64k][64i] | sB[64k][64j]; Cs reuses front
    float* sA = sm;
    float* sB = sm + 4096;

    int tid = threadIdx.x;

    // Load both tiles transposed into smem: s[k][row]
    for (int f = tid; f < 1024; f += 256) {
        int r = f >> 4;
        int k4 = (f & 15) * 4;
        float4 va = *(const float4*)(A  + (size_t)(i0 + r) * DDIM + k4);
        sA[(k4 + 0) * 64 + r] = va.x;
        sA[(k4 + 1) * 64 + r] = va.y;
        sA[(k4 + 2) * 64 + r] = va.z;
        sA[(k4 + 3) * 64 + r] = va.w;
        float4 vb = *(const float4*)(Bm + (size_t)(j0 + r) * DDIM + k4);
        sB[(k4 + 0) * 64 + r] = vb.x;
        sB[(k4 + 1) * 64 + r] = vb.y;
        sB[(k4 + 2) * 64 + r] = vb.z;
        sB[(k4 + 3) * 64 + r] = vb.w;
    }
    __syncthreads();

    int tx = tid & 15, ty = tid >> 4;
    float acc[16];
    #pragma unroll
    for (int i = 0; i < 16; ++i) acc[i] = 0.f;

    #pragma unroll 8
    for (int k = 0; k < 64; ++k) {
        float4 a  = *(const float4*)(sA + k * 64 + ty * 4);
        float4 bv = *(const float4*)(sB + k * 64 + tx * 4);
        acc[ 0] += a.x * bv.x;  acc[ 1] += a.x * bv.y;
        acc[ 2] += a.x * bv.z;  acc[ 3] += a.x * bv.w;
        acc[ 4] += a.y * bv.x;  acc[ 5] += a.y * bv.y;
        acc[ 6] += a.y * bv.z;  acc[ 7] += a.y * bv.w;
        acc[ 8] += a.z * bv.x;  acc[ 9] += a.z * bv.y;
        acc[10] += a.z * bv.z;  acc[11] += a.z * bv.w;
        acc[12] += a.w * bv.x;  acc[13] += a.w * bv.y;
        acc[14] += a.w * bv.z;  acc[15] += a.w * bv.w;
    }

    const float* a2p = g_n2 + b * TT;
    const float* b2p = g_n2 + BB * TT + b * TT;
    float a2v[4], b2v[4];
    #pragma unroll
    for (int e = 0; e < 4; ++e) a2v[e] = a2p[i0 + ty * 4 + e];
    #pragma unroll
    for (int f = 0; f < 4; ++f) b2v[f] = b2p[j0 + tx * 4 + f];

    __syncthreads();   // done reading sA/sB; reuse as Cs (stride 66: diag-gather conflict-free)
    float* Cs = sm;
    #pragma unroll
    for (int e = 0; e < 4; ++e) {
        #pragma unroll
        for (int f = 0; f < 4; ++f) {
            float sq = a2v[e] + b2v[f] - 2.0f * acc[e * 4 + f];
            Cs[(ty * 4 + e) * 66 + (tx * 4 + f)] = sqrtf(fmaxf(sq, 1e-12f));
        }
    }
    __syncthreads();

    // Diagonal-major writes: runs of up to 64 contiguous floats per tile-diagonal.
    float* out = g_cost + (size_t)b * 2048 * TT;
    int warp = tid >> 5, lane = tid & 31;
    int D0 = i0 + j0;
    for (int dd = warp; dd < 127; dd += 8) {
        int jl = max(0, dd - 63);
        int jh = min(dd, 63);
        int L = jh - jl + 1;
        size_t gb = (size_t)(D0 + dd) * TT + (size_t)(j0 + jl);
        for (int l = lane; l < L; l += 32) {
            int j = jl + l;
            out[gb + l] = Cs[(dd - j) * 66 + j];
        }
    }
}

// ---------------------------------------------------------------------------
// Kernel 3: anti-diagonal wavefront DP. One CTA per batch, 256 threads x 4 cells.
// Recurrence: ca = max(cost, min(up, left, diag)); boundaries carried as +INF,
// virtual ca[-1][-1] = -INF seeds (0,0). Neighbor values via 3-slot smem ring.
// ---------------------------------------------------------------------------
#define PF 8   // cost prefetch depth (covers DRAM latency across the barrier loop)

__global__ void __launch_bounds__(256, 1) dp_kernel() {
    int b = blockIdx.x;
    const float* SC = g_cost + (size_t)b * 2048 * TT;
    int t  = threadIdx.x;
    int j0 = t << 2;

    __shared__ float ring[3][264];   // ring[s][t+1] = cur[j0+3] at diag with d%3==s
    for (int idx = t; idx < 3 * 264; idx += 256) (&ring[0][0])[idx] = TINF;
    __syncthreads();

    float4 cbuf[PF];
    #pragma unroll
    for (int d = 0; d < PF; ++d)
        cbuf[d] = *(const float4*)(SC + (size_t)d * TT + j0);

    float p0 = TINF, p1 = TINF, p2 = TINF, p3 = TINF;   // diag d-1
    float q0 = TINF, q1 = TINF, q2 = TINF, q3 = TINF;   // diag d-2
    int s = 0;                                          // write slot = d%3

    for (int d = 0; d < NDIAG; ++d) {
        float4 c = cbuf[d & (PF - 1)];
        int dn = d + PF;
        if (dn < NDIAG)
            cbuf[d & (PF - 1)] = *(const float4*)(SC + (size_t)dn * TT + j0);

        int s1 = (s == 0) ? 2 : s - 1;     // slot of diag d-1
        int s2 = (s1 == 0) ? 2 : s1 - 1;   // slot of diag d-2
        float pm1 = ring[s1][t];           // prev[j0-1]  (thread t-1's last cell)
        float qm1 = ring[s2][t];           // prev2[j0-1]

        // Validity mask: cell (i=d-j, j) valid iff j<=d and j>=d-1023.
        int jlo = d - (TT - 1);
        float c0 = (j0 + 0 <= d && j0 + 0 >= jlo) ? c.x : TINF;
        float c1 = (j0 + 1 <= d && j0 + 1 >= jlo) ? c.y : TINF;
        float c2 = (j0 + 2 <= d && j0 + 2 >= jlo) ? c.z : TINF;
        float c3 = (j0 + 3 <= d && j0 + 3 >= jlo) ? c.w : TINF;

        float m0 = fminf(fminf(p0, pm1), qm1);
        float m1 = fminf(fminf(p1, p0), q0);
        float m2 = fminf(fminf(p2, p1), q1);
        float m3 = fminf(fminf(p3, p2), q2);
        if ((d | t) == 0) m0 = -TINF;      // seed: ca[0][0] = cost[0][0]

        float n0 = fmaxf(c0, m0);
        float n1 = fmaxf(c1, m1);
        float n2 = fmaxf(c2, m2);
        float n3 = fmaxf(c3, m3);

        ring[s][t + 1] = n3;
        __syncthreads();

        q0 = p0; q1 = p1; q2 = p2; q3 = p3;
        p0 = n0; p1 = n1; p2 = n2; p3 = n3;
        s = (s == 2) ? 0 : s + 1;
    }

    if (t == 255) g_bdist[b] = p3;   // ca[1023][1023]
}

// ---------------------------------------------------------------------------
// Kernel 4: mean over batches.
// ---------------------------------------------------------------------------
__global__ void reduce_kernel(float* out) {
    float v = g_bdist[threadIdx.x];
    #pragma unroll
    for (int o = 16; o > 0; o >>= 1) v += __shfl_down_sync(0xffffffffu, v, o);
    if (threadIdx.x == 0) out[0] = v * (1.0f / BB);
}

// ---------------------------------------------------------------------------
extern "C" void kernel_launch(void* const* d_in, const int* in_sizes, int n_in,
                              void* d_out, int out_size) {
    const float* pred = (const float*)d_in[0];
    const float* targ = (const float*)d_in[1];
    (void)in_sizes; (void)n_in; (void)out_size;

    norms_kernel<<<8192, 256>>>(pred, targ);          // 65536 rows, 8 warps/block
    dim3 cg(16, 16, 32);
    cost_kernel<<<cg, 256>>>(pred, targ);
    dp_kernel<<<32, 256>>>();
    reduce_kernel<<<1, 32>>>((float*)d_out);
}

// round 2
// speedup vs baseline: 2.9051x; 2.9051x over previous
#include <cuda_runtime.h>
#include <math.h>

#define TINF 3.0e38f
#define TT   1024
#define BB   32
#define DDIM 64
#define NDIAG (2*TT-1)   // 2047
#define PF   8           // cost prefetch depth (register ring)
#define UNR  24          // lcm(PF, 3) -> all ring indices static under unroll
#define NDLOOP 2064      // 86*24 >= NDIAG, extra diagonals fully masked

// Scratch: diag-major cost [b][d][j], d padded to 2048, plus 32-diag tail pad
// so the deepest prefetch (d+PF <= 2071) of the last batch stays in bounds.
__device__ float g_cost[(size_t)BB * 2048 * TT + 32 * TT];
__device__ float g_n2[2 * BB * TT];   // a2 (first half) then b2
__device__ float g_bdist[BB];

// ---------------------------------------------------------------------------
// Kernel 1: squared row norms. One warp per 64-dim row.
// ---------------------------------------------------------------------------
__global__ void norms_kernel(const float* __restrict__ pred,
                             const float* __restrict__ targ) {
    int gw   = (blockIdx.x * blockDim.x + threadIdx.x) >> 5;  // global warp id
    int lane = threadIdx.x & 31;
    if (gw >= 2 * BB * TT) return;
    const float* src = (gw < BB * TT) ? (pred + (size_t)gw * DDIM)
                                      : (targ + (size_t)(gw - BB * TT) * DDIM);
    float x0 = src[lane], x1 = src[lane + 32];
    float s = x0 * x0 + x1 * x1;
    #pragma unroll
    for (int o = 16; o > 0; o >>= 1) s += __shfl_down_sync(0xffffffffu, s, o);
    if (lane == 0) g_n2[gw] = s;
}

// ---------------------------------------------------------------------------
// Kernel 2: cost tiles. 64x64 tile per block (256 threads, 4x4 microtile),
// epilogue stages the tile in smem and writes diagonal-major runs (coalesced).
// ---------------------------------------------------------------------------
__global__ void __launch_bounds__(256) cost_kernel(const float* __restrict__ pred,
                                                   const float* __restrict__ targ) {
    int jt = blockIdx.x, it = blockIdx.y, b = blockIdx.z;
    int i0 = it * 64, j0 = jt * 64;
    const float* A  = pred + (size_t)b * TT * DDIM;
    const float* Bm = targ + (size_t)b * TT * DDIM;

    __shared__ float sm[8192];          // sA[64k][64i] | sB[64k][64j]; Cs reuses front
    float* sA = sm;
    float* sB = sm + 4096;

    int tid = threadIdx.x;

    // Load both tiles transposed into smem: s[k][row]
    for (int f = tid; f < 1024; f += 256) {
        int r = f >> 4;
        int k4 = (f & 15) * 4;
        float4 va = *(const float4*)(A  + (size_t)(i0 + r) * DDIM + k4);
        sA[(k4 + 0) * 64 + r] = va.x;
        sA[(k4 + 1) * 64 + r] = va.y;
        sA[(k4 + 2) * 64 + r] = va.z;
        sA[(k4 + 3) * 64 + r] = va.w;
        float4 vb = *(const float4*)(Bm + (size_t)(j0 + r) * DDIM + k4);
        sB[(k4 + 0) * 64 + r] = vb.x;
        sB[(k4 + 1) * 64 + r] = vb.y;
        sB[(k4 + 2) * 64 + r] = vb.z;
        sB[(k4 + 3) * 64 + r] = vb.w;
    }
    __syncthreads();

    int tx = tid & 15, ty = tid >> 4;
    float acc[16];
    #pragma unroll
    for (int i = 0; i < 16; ++i) acc[i] = 0.f;

    #pragma unroll 8
    for (int k = 0; k < 64; ++k) {
        float4 a  = *(const float4*)(sA + k * 64 + ty * 4);
        float4 bv = *(const float4*)(sB + k * 64 + tx * 4);
        acc[ 0] += a.x * bv.x;  acc[ 1] += a.x * bv.y;
        acc[ 2] += a.x * bv.z;  acc[ 3] += a.x * bv.w;
        acc[ 4] += a.y * bv.x;  acc[ 5] += a.y * bv.y;
        acc[ 6] += a.y * bv.z;  acc[ 7] += a.y * bv.w;
        acc[ 8] += a.z * bv.x;  acc[ 9] += a.z * bv.y;
        acc[10] += a.z * bv.z;  acc[11] += a.z * bv.w;
        acc[12] += a.w * bv.x;  acc[13] += a.w * bv.y;
        acc[14] += a.w * bv.z;  acc[15] += a.w * bv.w;
    }

    const float* a2p = g_n2 + b * TT;
    const float* b2p = g_n2 + BB * TT + b * TT;
    float a2v[4], b2v[4];
    #pragma unroll
    for (int e = 0; e < 4; ++e) a2v[e] = a2p[i0 + ty * 4 + e];
    #pragma unroll
    for (int f = 0; f < 4; ++f) b2v[f] = b2p[j0 + tx * 4 + f];

    __syncthreads();   // done reading sA/sB; reuse as Cs (stride 66: diag-gather conflict-free)
    float* Cs = sm;
    #pragma unroll
    for (int e = 0; e < 4; ++e) {
        #pragma unroll
        for (int f = 0; f < 4; ++f) {
            float sq = a2v[e] + b2v[f] - 2.0f * acc[e * 4 + f];
            Cs[(ty * 4 + e) * 66 + (tx * 4 + f)] = sqrtf(fmaxf(sq, 1e-12f));
        }
    }
    __syncthreads();

    // Diagonal-major writes: runs of up to 64 contiguous floats per tile-diagonal.
    float* out = g_cost + (size_t)b * 2048 * TT;
    int warp = tid >> 5, lane = tid & 31;
    int D0 = i0 + j0;
    for (int dd = warp; dd < 127; dd += 8) {
        int jl = max(0, dd - 63);
        int jh = min(dd, 63);
        int L = jh - jl + 1;
        size_t gb = (size_t)(D0 + dd) * TT + (size_t)(j0 + jl);
        for (int l = lane; l < L; l += 32) {
            int j = jl + l;
            out[gb + l] = Cs[(dd - j) * 66 + j];
        }
    }
}

// ---------------------------------------------------------------------------
// Kernel 3: anti-diagonal wavefront DP. One CTA per batch, 256 threads x 4 cells.
// Recurrence: ca = max(cost, min(up, left, diag)); boundaries carried as +INF,
// virtual ca[-1][-1] = -INF seeds (0,0). Neighbor values via 3-slot smem ring.
// Loop unrolled by 24 = lcm(PF, 3) so BOTH the register prefetch-ring index
// (u & 7) and the smem ring slot (u % 3) are compile-time constants -> cbuf
// stays in registers (no local-memory demotion), true MLP=8 prefetch.
// ---------------------------------------------------------------------------
__global__ void __launch_bounds__(256, 1) dp_kernel() {
    int b = blockIdx.x;
    const float* SC = g_cost + (size_t)b * 2048 * TT;
    int t  = threadIdx.x;
    int j0 = t << 2;

    __shared__ float ring[3][264];   // ring[s][t+1] = cur[j0+3] at diag with d%3==s
    for (int idx = t; idx < 3 * 264; idx += 256) (&ring[0][0])[idx] = TINF;
    __syncthreads();

    float4 cbuf[PF];
    #pragma unroll
    for (int d = 0; d < PF; ++d)
        cbuf[d] = *(const float4*)(SC + (size_t)d * TT + j0);

    float p0 = TINF, p1 = TINF, p2 = TINF, p3 = TINF;   // diag d-1
    float q0 = TINF, q1 = TINF, q2 = TINF, q3 = TINF;   // diag d-2
    float res = 0.f;

    for (int db = 0; db < NDLOOP; db += UNR) {
        #pragma unroll
        for (int u = 0; u < UNR; ++u) {
            int d = db + u;
            float4 c = cbuf[u & (PF - 1)];                 // static index
            cbuf[u & (PF - 1)] =                           // prefetch d+PF
                *(const float4*)(SC + (size_t)(d + PF) * TT + j0);

            const int s  = u % 3;                          // static slot = d%3
            const int s1 = (s + 2) % 3;                    // diag d-1
            const int s2 = (s + 1) % 3;                    // diag d-2
            float pm1 = ring[s1][t];                       // prev[j0-1]
            float qm1 = ring[s2][t];                       // prev2[j0-1]

            // Validity: cell (i=d-j, j) valid iff j<=d and j>=d-1023.
            int jlo = d - (TT - 1);
            float c0 = (j0 + 0 <= d && j0 + 0 >= jlo) ? c.x : TINF;
            float c1 = (j0 + 1 <= d && j0 + 1 >= jlo) ? c.y : TINF;
            float c2 = (j0 + 2 <= d && j0 + 2 >= jlo) ? c.z : TINF;
            float c3 = (j0 + 3 <= d && j0 + 3 >= jlo) ? c.w : TINF;

            float m0 = fminf(fminf(p0, pm1), qm1);
            float m1 = fminf(fminf(p1, p0), q0);
            float m2 = fminf(fminf(p2, p1), q1);
            float m3 = fminf(fminf(p3, p2), q2);
            if ((d | t) == 0) m0 = -TINF;                  // seed ca[0][0]=cost[0][0]

            float n0 = fmaxf(c0, m0);
            float n1 = fmaxf(c1, m1);
            float n2 = fmaxf(c2, m2);
            float n3 = fmaxf(c3, m3);

            ring[s][t + 1] = n3;
            __syncthreads();

            if (d == NDIAG - 1) res = n3;                  // latch ca[1023][1023]

            q0 = p0; q1 = p1; q2 = p2; q3 = p3;
            p0 = n0; p1 = n1; p2 = n2; p3 = n3;
        }
    }

    if (t == 255) g_bdist[b] = res;
}

// ---------------------------------------------------------------------------
// Kernel 4: mean over batches.
// ---------------------------------------------------------------------------
__global__ void reduce_kernel(float* out) {
    float v = g_bdist[threadIdx.x];
    #pragma unroll
    for (int o = 16; o > 0; o >>= 1) v += __shfl_down_sync(0xffffffffu, v, o);
    if (threadIdx.x == 0) out[0] = v * (1.0f / BB);
}

// ---------------------------------------------------------------------------
extern "C" void kernel_launch(void* const* d_in, const int* in_sizes, int n_in,
                              void* d_out, int out_size) {
    const float* pred = (const float*)d_in[0];
    const float* targ = (const float*)d_in[1];
    (void)in_sizes; (void)n_in; (void)out_size;

    norms_kernel<<<8192, 256>>>(pred, targ);          // 65536 rows, 8 warps/block
    dim3 cg(16, 16, 32);
    cost_kernel<<<cg, 256>>>(pred, targ);
    dp_kernel<<<32, 256>>>();
    reduce_kernel<<<1, 32>>>((float*)d_out);
}